// round 16
// baseline (speedup 1.0000x reference)
#include <cuda_runtime.h>

#define NND 100000
#define NE  1250000
#define HID 64
#define CSR_BLOCKS 98
#define CSR_THREADS 1024

#define APSTRIDE1 66   // sAp pair stride in ulls (K=64 + pad)

// ---------------- scratch (device globals; no allocation allowed) ----------
__device__ float g_h0[NND * HID];
__device__ float g_h1[NND * HID];
__device__ float g_agg[NND * HID];
__device__ int   g_cnt[NND];
__device__ int   g_rowstart[NND];
__device__ int   g_cursor[NND];
__device__ int   g_adj[NE];
__device__ int   g_blocksum[CSR_BLOCKS];
__device__ int   g_bar_count;
__device__ int   g_bar_sense;

typedef unsigned long long ull;

__device__ __forceinline__ ull pack2(float v) {
    ull r; asm("mov.b64 %0, {%1, %1};" : "=l"(r) : "f"(v)); return r;
}
__device__ __forceinline__ ull packf2(float lo, float hi) {
    ull r; asm("mov.b64 %0, {%1, %2};" : "=l"(r) : "f"(lo), "f"(hi)); return r;
}
__device__ __forceinline__ void fma2(ull& d, ull a, ull b) {
    asm("fma.rn.f32x2 %0, %1, %2, %0;" : "+l"(d) : "l"(a), "l"(b));
}
__device__ __forceinline__ float2 unpk(ull v) {
    float2 r; asm("mov.b64 {%0, %1}, %2;" : "=f"(r.x), "=f"(r.y) : "l"(v)); return r;
}
__device__ __forceinline__ float prelu(float v, float a) { return v >= 0.f ? v : a * v; }

// ---------------- launch 1: gather h0 + zero cnt + reset barrier ------------
__global__ void prep_kernel(const int* __restrict__ x,
                            const float* __restrict__ emb,
                            float* __restrict__ h0) {
    int t = blockIdx.x * blockDim.x + threadIdx.x;
    if (t < NND) g_cnt[t] = 0;
    if (t == 0) { g_bar_count = 0; g_bar_sense = 0; }
    int i = t >> 4;
    int p = (t & 15) << 2;
    int xi = __ldg(&x[i]);
    *(float4*)&h0[i * HID + p] = *(const float4*)&emb[xi * HID + p];
}

// ---------------- software grid barrier -------------------------------------
__device__ __forceinline__ void grid_barrier(int phase) {
    __threadfence();
    __syncthreads();
    if (threadIdx.x == 0) {
        int v = atomicAdd(&g_bar_count, 1);
        if (v == CSR_BLOCKS - 1) {
            atomicExch(&g_bar_count, 0);
            __threadfence();
            atomicExch(&g_bar_sense, phase);
        } else {
            while (true) {
                int s;
                asm volatile("ld.global.cg.s32 %0, [%1];" : "=r"(s) : "l"(&g_bar_sense));
                if (s >= phase) break;
                __nanosleep(64);
            }
        }
    }
    __syncthreads();
}

// ---------------- launch 2: persistent CSR build (count+scan+fill) ----------
__global__ __launch_bounds__(CSR_THREADS) void csr_kernel(const int* __restrict__ ei) {
    const int tid = threadIdx.x, bid = blockIdx.x;
    const int gid = bid * CSR_THREADS + tid;
    const int gstride = CSR_BLOCKS * CSR_THREADS;

    for (int e = gid; e < NE; e += gstride)
        atomicAdd(&g_cnt[__ldg(&ei[NE + e])], 1);
    grid_barrier(1);

    __shared__ int swarp[32];
    __shared__ int soff[CSR_BLOCKS];
    int v = 0;
    if (gid < NND)
        asm volatile("ld.global.cg.s32 %0, [%1];" : "=r"(v) : "l"(&g_cnt[gid]));
    const int lane = tid & 31, wid = tid >> 5;
    int x = v;
    #pragma unroll
    for (int d = 1; d < 32; d <<= 1) { int t = __shfl_up_sync(~0u, x, d); if (lane >= d) x += t; }
    if (lane == 31) swarp[wid] = x;
    __syncthreads();
    if (wid == 0) {
        int y = swarp[lane];
        int z = y;
        #pragma unroll
        for (int d = 1; d < 32; d <<= 1) { int t = __shfl_up_sync(~0u, z, d); if (lane >= d) z += t; }
        swarp[lane] = z - y;
    }
    __syncthreads();
    const int excl = x - v + swarp[wid];
    if (tid == CSR_THREADS - 1) g_blocksum[bid] = excl + v;
    grid_barrier(2);

    if (tid < CSR_BLOCKS) {
        int b;
        asm volatile("ld.global.cg.s32 %0, [%1];" : "=r"(b) : "l"(&g_blocksum[tid]));
        soff[tid] = b;
    }
    __syncthreads();
    if (tid == 0) {
        int run = 0;
        for (int i = 0; i < CSR_BLOCKS; i++) { int t = soff[i]; soff[i] = run; run += t; }
    }
    __syncthreads();
    if (gid < NND) {
        int st = excl + soff[bid];
        g_rowstart[gid] = st;
        g_cursor[gid] = st;
    }
    grid_barrier(3);

    for (int e = gid; e < NE; e += gstride) {
        int src = __ldg(&ei[e]);
        int dst = __ldg(&ei[NE + e]);
        int pp = atomicAdd(&g_cursor[dst], 1);
        g_adj[pp] = src;
    }
}

// ---------------- mean aggregation (prefetched adj batches) -----------------
__global__ __launch_bounds__(256) void agg_kernel(const float* __restrict__ h,
                                                  float* __restrict__ aggout) {
    const int tid = threadIdx.x;
    const int gid = blockIdx.x * 256 + tid;
    const int node = gid >> 4;
    if (node >= NND) return;
    const int lane16 = tid & 15;
    const int p4 = lane16 << 2;
    const unsigned smask = 0xFFFFu << (tid & 16);

    const int st = __ldg(&g_rowstart[node]);
    const int n  = __ldg(&g_cnt[node]);
    float4 acc = make_float4(0.f, 0.f, 0.f, 0.f);

    int idx = 0;
    if (n > 0 && lane16 < n) idx = __ldg(&g_adj[st + lane16]);

    for (int j = 0; j < n; j += 16) {
        const int m = min(16, n - j);
        int idx_next = 0;
        const int jn = j + 16;
        if (jn < n && lane16 < n - jn) idx_next = __ldg(&g_adj[st + jn + lane16]);

        int jj = 0;
        for (; jj + 4 <= m; jj += 4) {
            int s0 = __shfl_sync(smask, idx, jj + 0, 16);
            int s1 = __shfl_sync(smask, idx, jj + 1, 16);
            int s2 = __shfl_sync(smask, idx, jj + 2, 16);
            int s3 = __shfl_sync(smask, idx, jj + 3, 16);
            float4 v0 = *(const float4*)&h[s0 * HID + p4];
            float4 v1 = *(const float4*)&h[s1 * HID + p4];
            float4 v2 = *(const float4*)&h[s2 * HID + p4];
            float4 v3 = *(const float4*)&h[s3 * HID + p4];
            acc.x += (v0.x + v1.x) + (v2.x + v3.x);
            acc.y += (v0.y + v1.y) + (v2.y + v3.y);
            acc.z += (v0.z + v1.z) + (v2.z + v3.z);
            acc.w += (v0.w + v1.w) + (v2.w + v3.w);
        }
        for (; jj < m; jj++) {
            int s0 = __shfl_sync(smask, idx, jj, 16);
            float4 v0 = *(const float4*)&h[s0 * HID + p4];
            acc.x += v0.x; acc.y += v0.y; acc.z += v0.z; acc.w += v0.w;
        }
        idx = idx_next;
    }
    const float iv = 1.0f / (float)max(n, 1);
    *(float4*)&aggout[node * HID + p4] =
        make_float4(acc.x * iv, acc.y * iv, acc.z * iv, acc.w * iv);
}

// ---------------- K=64 GEMM pass (single-shape, 4 CTAs/SM) -------------------
// out = A @ W (+ bias | + acc_in) [, prelu]
// ACCUM=false: acc init = bias bb. ACCUM=true: acc init = acc_in rows.
// chunk = 128 nodes = 64 pairs; smem = 16KB W + ~34KB A = ~50KB.
template<bool ACCUM, bool PRELU>
__global__ __launch_bounds__(256, 4) void gemm_pass_kernel(
    const float* __restrict__ A, const float* __restrict__ W,
    const float* __restrict__ bb, const float* __restrict__ acc_in,
    const float* __restrict__ alpha_p, float* __restrict__ out)
{
    extern __shared__ float sm[];
    float* sW = sm;                                  // 64*64
    ull*   sAp = (ull*)(sW + 64 * 64);               // 64 pairs * APSTRIDE1

    const int tid = threadIdx.x;
    #pragma unroll
    for (int t = tid; t < 64 * 16; t += 256) {
        int k = t >> 4, q = (t & 15) << 2;
        *(float4*)&sW[k * 64 + q] = __ldg((const float4*)&W[k * HID + q]);
    }

    float alpha = 0.f;
    if (PRELU) alpha = __ldg(alpha_p);

    const int lane  = tid & 31;
    const int wid   = tid >> 5;
    const int half  = lane >> 4;
    const int lane16 = lane & 15;
    const int pbase = (wid << 3) + (half << 2);      // 4 pairs per half
    const int c4 = lane16 << 2;                      // 4 cols per lane
    const int nchunks = (NND + 127) / 128;           // 782

    for (int chunk = blockIdx.x; chunk < nchunks; chunk += gridDim.x) {
        const int base = chunk * 128;
        __syncthreads();   // sAp free (covers sW staging on first iteration)
        #pragma unroll
        for (int it = 0; it < 4; it++) {
            int idx = it * 256 + tid;
            int p  = idx >> 4;
            int kq = (idx & 15) << 2;
            int n0 = base + (p << 1), n1 = n0 + 1;
            float4 a0 = make_float4(0.f, 0.f, 0.f, 0.f);
            float4 a1 = make_float4(0.f, 0.f, 0.f, 0.f);
            if (n0 < NND) a0 = *(const float4*)&A[n0 * HID + kq];
            if (n1 < NND) a1 = *(const float4*)&A[n1 * HID + kq];
            ull* dst = &sAp[p * APSTRIDE1 + kq];
            dst[0] = packf2(a0.x, a1.x);
            dst[1] = packf2(a0.y, a1.y);
            dst[2] = packf2(a0.z, a1.z);
            dst[3] = packf2(a0.w, a1.w);
        }
        __syncthreads();

        ull acc[4][4];
        if (ACCUM) {
            #pragma unroll
            for (int i = 0; i < 4; i++) {
                int n0 = base + ((pbase + i) << 1), n1 = n0 + 1;
                float4 t0 = make_float4(0.f, 0.f, 0.f, 0.f);
                float4 t1 = make_float4(0.f, 0.f, 0.f, 0.f);
                if (n0 < NND) t0 = __ldg((const float4*)&acc_in[n0 * HID + c4]);
                if (n1 < NND) t1 = __ldg((const float4*)&acc_in[n1 * HID + c4]);
                acc[i][0] = packf2(t0.x, t1.x);
                acc[i][1] = packf2(t0.y, t1.y);
                acc[i][2] = packf2(t0.z, t1.z);
                acc[i][3] = packf2(t0.w, t1.w);
            }
        } else {
            float4 bv = __ldg((const float4*)&bb[c4]);
            #pragma unroll
            for (int i = 0; i < 4; i++) {
                acc[i][0] = pack2(bv.x); acc[i][1] = pack2(bv.y);
                acc[i][2] = pack2(bv.z); acc[i][3] = pack2(bv.w);
            }
        }

        #pragma unroll 4
        for (int kb = 0; kb < 64; kb += 2) {
            float4 w0 = *(const float4*)&sW[kb * 64 + c4];
            float4 w1 = *(const float4*)&sW[(kb + 1) * 64 + c4];
            ull wp0[4] = { pack2(w0.x), pack2(w0.y), pack2(w0.z), pack2(w0.w) };
            ull wp1[4] = { pack2(w1.x), pack2(w1.y), pack2(w1.z), pack2(w1.w) };
            ulonglong2 Ap[4];
            #pragma unroll
            for (int i = 0; i < 4; i++)
                Ap[i] = *(const ulonglong2*)&sAp[(pbase + i) * APSTRIDE1 + kb];
            #pragma unroll
            for (int i = 0; i < 4; i++) {
                fma2(acc[i][0], Ap[i].x, wp0[0]); fma2(acc[i][1], Ap[i].x, wp0[1]);
                fma2(acc[i][2], Ap[i].x, wp0[2]); fma2(acc[i][3], Ap[i].x, wp0[3]);
                fma2(acc[i][0], Ap[i].y, wp1[0]); fma2(acc[i][1], Ap[i].y, wp1[1]);
                fma2(acc[i][2], Ap[i].y, wp1[2]); fma2(acc[i][3], Ap[i].y, wp1[3]);
            }
        }

        #pragma unroll
        for (int i = 0; i < 4; i++) {
            int n0 = base + ((pbase + i) << 1), n1 = n0 + 1;
            float2 v0 = unpk(acc[i][0]), v1 = unpk(acc[i][1]);
            float2 v2 = unpk(acc[i][2]), v3 = unpk(acc[i][3]);
            if (PRELU) {
                v0.x = prelu(v0.x, alpha); v0.y = prelu(v0.y, alpha);
                v1.x = prelu(v1.x, alpha); v1.y = prelu(v1.y, alpha);
                v2.x = prelu(v2.x, alpha); v2.y = prelu(v2.y, alpha);
                v3.x = prelu(v3.x, alpha); v3.y = prelu(v3.y, alpha);
            }
            if (n0 < NND)
                *(float4*)&out[n0 * HID + c4] = make_float4(v0.x, v1.x, v2.x, v3.x);
            if (n1 < NND)
                *(float4*)&out[n1 * HID + c4] = make_float4(v0.y, v1.y, v2.y, v3.y);
        }
    }
}

// ---------------- launch -----------------------------------------------------
extern "C" void kernel_launch(void* const* d_in, const int* in_sizes, int n_in,
                              void* d_out, int out_size) {
    const int*   x    = (const int*)d_in[0];
    const int*   ei   = (const int*)d_in[1];
    // d_in[2] = edge_weight : unused by the reference
    const float* emb  = (const float*)d_in[3];
    const float* Wl1  = (const float*)d_in[4];
    const float* bl1  = (const float*)d_in[5];
    const float* Wr1  = (const float*)d_in[6];
    const float* a1   = (const float*)d_in[7];
    const float* Wl2  = (const float*)d_in[8];
    const float* bl2  = (const float*)d_in[9];
    const float* Wr2  = (const float*)d_in[10];
    const float* a2   = (const float*)d_in[11];
    const float* Wout = (const float*)d_in[12];
    const float* bout = (const float*)d_in[13];
    float* out = (float*)d_out;

    float *h0, *h1, *agg;
    cudaGetSymbolAddress((void**)&h0,  g_h0);
    cudaGetSymbolAddress((void**)&h1,  g_h1);
    cudaGetSymbolAddress((void**)&agg, g_agg);

    const size_t smem_gemm = 64 * 64 * sizeof(float) + 64 * APSTRIDE1 * sizeof(ull); // ~50KB
    cudaFuncSetAttribute(gemm_pass_kernel<false, false>,
                         cudaFuncAttributeMaxDynamicSharedMemorySize, (int)smem_gemm);
    cudaFuncSetAttribute(gemm_pass_kernel<true, true>,
                         cudaFuncAttributeMaxDynamicSharedMemorySize, (int)smem_gemm);

    const int g_agg_grid = (NND * 16) / 256;   // 6250
    const int g_gemm = 782;                     // one chunk per CTA

    prep_kernel<<<g_agg_grid, 256>>>(x, emb, h0);
    csr_kernel<<<CSR_BLOCKS, CSR_THREADS>>>(ei);

    // layer 1: agg -> tmp = agg@Wl1 + bl1 (in-place) -> h1 = prelu(h0@Wr1 + tmp)
    agg_kernel<<<g_agg_grid, 256>>>(h0, agg);
    gemm_pass_kernel<false, false><<<g_gemm, 256, smem_gemm>>>(
        agg, Wl1, bl1, nullptr, nullptr, agg);
    gemm_pass_kernel<true, true><<<g_gemm, 256, smem_gemm>>>(
        h0, Wr1, nullptr, agg, a1, h1);

    // layer 2: same, h2 -> h0 buffer
    agg_kernel<<<g_agg_grid, 256>>>(h1, agg);
    gemm_pass_kernel<false, false><<<g_gemm, 256, smem_gemm>>>(
        agg, Wl2, bl2, nullptr, nullptr, agg);
    gemm_pass_kernel<true, true><<<g_gemm, 256, smem_gemm>>>(
        h1, Wr2, nullptr, agg, a2, h0);

    // output projection
    gemm_pass_kernel<false, false><<<g_gemm, 256, smem_gemm>>>(
        h0, Wout, bout, nullptr, nullptr, out);
}

// round 17
// speedup vs baseline: 1.0412x; 1.0412x over previous
#include <cuda_runtime.h>

#define NND 100000
#define NE  1250000
#define HID 64
#define CSR_BLOCKS 98
#define CSR_THREADS 1024

#define APSTRIDE1 66   // sAp pair stride in ulls (K=64 + pad)

// ---------------- scratch (device globals; no allocation allowed) ----------
__device__ float g_h0[NND * HID];
__device__ float g_h1[NND * HID];
__device__ float g_agg[NND * HID];
__device__ float g_tmp[NND * HID];
__device__ int   g_cnt[NND];
__device__ int   g_rowstart[NND];
__device__ int   g_cursor[NND];
__device__ int   g_adj[NE];
__device__ int   g_blocksum[CSR_BLOCKS];
__device__ int   g_bar_count;   // static-zero; barrier self-resets
__device__ int   g_bar_sense;   // monotonic; never reset

typedef unsigned long long ull;

__device__ __forceinline__ ull pack2(float v) {
    ull r; asm("mov.b64 %0, {%1, %1};" : "=l"(r) : "f"(v)); return r;
}
__device__ __forceinline__ ull packf2(float lo, float hi) {
    ull r; asm("mov.b64 %0, {%1, %2};" : "=l"(r) : "f"(lo), "f"(hi)); return r;
}
__device__ __forceinline__ void fma2(ull& d, ull a, ull b) {
    asm("fma.rn.f32x2 %0, %1, %2, %0;" : "+l"(d) : "l"(a), "l"(b));
}
__device__ __forceinline__ float2 unpk(ull v) {
    float2 r; asm("mov.b64 {%0, %1}, %2;" : "=f"(r.x), "=f"(r.y) : "l"(v)); return r;
}
__device__ __forceinline__ float prelu(float v, float a) { return v >= 0.f ? v : a * v; }

// ---------------- embedding gather (pure) ------------------------------------
__global__ void prep_kernel(const int* __restrict__ x,
                            const float* __restrict__ emb,
                            float* __restrict__ h0) {
    int t = blockIdx.x * blockDim.x + threadIdx.x;
    int i = t >> 4;
    int p = (t & 15) << 2;
    int xi = __ldg(&x[i]);
    *(float4*)&h0[i * HID + p] = *(const float4*)&emb[xi * HID + p];
}

// ---------------- monotonic-sense grid barrier (replay-safe) ----------------
__device__ __forceinline__ void grid_barrier(int s0, int k) {
    __threadfence();
    __syncthreads();
    if (threadIdx.x == 0) {
        int v = atomicAdd(&g_bar_count, 1);
        if (v == CSR_BLOCKS - 1) {
            atomicExch(&g_bar_count, 0);
            __threadfence();
            atomicExch(&g_bar_sense, s0 + k);
        } else {
            while (true) {
                int s;
                asm volatile("ld.global.cg.s32 %0, [%1];" : "=r"(s) : "l"(&g_bar_sense));
                if ((int)(s - s0) >= k) break;
                __nanosleep(64);
            }
        }
    }
    __syncthreads();
}

// ---------------- persistent CSR build (zero+count+scan+fill) ----------------
__global__ __launch_bounds__(CSR_THREADS) void csr_kernel(const int* __restrict__ ei) {
    const int tid = threadIdx.x, bid = blockIdx.x;
    const int gid = bid * CSR_THREADS + tid;
    const int gstride = CSR_BLOCKS * CSR_THREADS;

    int s0;
    asm volatile("ld.global.cg.s32 %0, [%1];" : "=r"(s0) : "l"(&g_bar_sense));

    // phase 0: zero degree counts
    for (int i = gid; i < NND; i += gstride) g_cnt[i] = 0;
    grid_barrier(s0, 1);

    // phase 1: degree count
    for (int e = gid; e < NE; e += gstride)
        atomicAdd(&g_cnt[__ldg(&ei[NE + e])], 1);
    grid_barrier(s0, 2);

    // phase 2: intra-block exclusive scan
    __shared__ int swarp[32];
    __shared__ int soff[CSR_BLOCKS];
    int v = 0;
    if (gid < NND)
        asm volatile("ld.global.cg.s32 %0, [%1];" : "=r"(v) : "l"(&g_cnt[gid]));
    const int lane = tid & 31, wid = tid >> 5;
    int xsc = v;
    #pragma unroll
    for (int d = 1; d < 32; d <<= 1) { int t = __shfl_up_sync(~0u, xsc, d); if (lane >= d) xsc += t; }
    if (lane == 31) swarp[wid] = xsc;
    __syncthreads();
    if (wid == 0) {
        int y = swarp[lane];
        int z = y;
        #pragma unroll
        for (int d = 1; d < 32; d <<= 1) { int t = __shfl_up_sync(~0u, z, d); if (lane >= d) z += t; }
        swarp[lane] = z - y;
    }
    __syncthreads();
    const int excl = xsc - v + swarp[wid];
    if (tid == CSR_THREADS - 1) g_blocksum[bid] = excl + v;
    grid_barrier(s0, 3);

    // phase 3: cross-block offsets -> rowstart + cursor
    if (tid < CSR_BLOCKS) {
        int b;
        asm volatile("ld.global.cg.s32 %0, [%1];" : "=r"(b) : "l"(&g_blocksum[tid]));
        soff[tid] = b;
    }
    __syncthreads();
    if (tid == 0) {
        int run = 0;
        for (int i = 0; i < CSR_BLOCKS; i++) { int t = soff[i]; soff[i] = run; run += t; }
    }
    __syncthreads();
    if (gid < NND) {
        int st = excl + soff[bid];
        g_rowstart[gid] = st;
        g_cursor[gid] = st;
    }
    grid_barrier(s0, 4);

    // phase 4: bucket fill
    for (int e = gid; e < NE; e += gstride) {
        int src = __ldg(&ei[e]);
        int dst = __ldg(&ei[NE + e]);
        int pp = atomicAdd(&g_cursor[dst], 1);
        g_adj[pp] = src;
    }
}

// ---------------- mean aggregation (prefetched adj batches) -----------------
__global__ __launch_bounds__(256) void agg_kernel(const float* __restrict__ h,
                                                  float* __restrict__ aggout) {
    const int tid = threadIdx.x;
    const int gid = blockIdx.x * 256 + tid;
    const int node = gid >> 4;
    if (node >= NND) return;
    const int lane16 = tid & 15;
    const int p4 = lane16 << 2;
    const unsigned smask = 0xFFFFu << (tid & 16);

    const int st = __ldg(&g_rowstart[node]);
    const int n  = __ldg(&g_cnt[node]);
    float4 acc = make_float4(0.f, 0.f, 0.f, 0.f);

    int idx = 0;
    if (n > 0 && lane16 < n) idx = __ldg(&g_adj[st + lane16]);

    for (int j = 0; j < n; j += 16) {
        const int m = min(16, n - j);
        int idx_next = 0;
        const int jn = j + 16;
        if (jn < n && lane16 < n - jn) idx_next = __ldg(&g_adj[st + jn + lane16]);

        int jj = 0;
        for (; jj + 4 <= m; jj += 4) {
            int s0 = __shfl_sync(smask, idx, jj + 0, 16);
            int s1 = __shfl_sync(smask, idx, jj + 1, 16);
            int s2 = __shfl_sync(smask, idx, jj + 2, 16);
            int s3 = __shfl_sync(smask, idx, jj + 3, 16);
            float4 v0 = *(const float4*)&h[s0 * HID + p4];
            float4 v1 = *(const float4*)&h[s1 * HID + p4];
            float4 v2 = *(const float4*)&h[s2 * HID + p4];
            float4 v3 = *(const float4*)&h[s3 * HID + p4];
            acc.x += (v0.x + v1.x) + (v2.x + v3.x);
            acc.y += (v0.y + v1.y) + (v2.y + v3.y);
            acc.z += (v0.z + v1.z) + (v2.z + v3.z);
            acc.w += (v0.w + v1.w) + (v2.w + v3.w);
        }
        for (; jj < m; jj++) {
            int s0 = __shfl_sync(smask, idx, jj, 16);
            float4 v0 = *(const float4*)&h[s0 * HID + p4];
            acc.x += v0.x; acc.y += v0.y; acc.z += v0.z; acc.w += v0.w;
        }
        idx = idx_next;
    }
    const float iv = 1.0f / (float)max(n, 1);
    *(float4*)&aggout[node * HID + p4] =
        make_float4(acc.x * iv, acc.y * iv, acc.z * iv, acc.w * iv);
}

// ---------------- K=64 GEMM pass (single-shape, 4 CTAs/SM) -------------------
template<bool ACCUM, bool PRELU>
__global__ __launch_bounds__(256, 4) void gemm_pass_kernel(
    const float* __restrict__ A, const float* __restrict__ W,
    const float* __restrict__ bb, const float* __restrict__ acc_in,
    const float* __restrict__ alpha_p, float* __restrict__ out)
{
    extern __shared__ float sm[];
    float* sW = sm;                                  // 64*64
    ull*   sAp = (ull*)(sW + 64 * 64);               // 64 pairs * APSTRIDE1

    const int tid = threadIdx.x;
    #pragma unroll
    for (int t = tid; t < 64 * 16; t += 256) {
        int k = t >> 4, q = (t & 15) << 2;
        *(float4*)&sW[k * 64 + q] = __ldg((const float4*)&W[k * HID + q]);
    }

    float alpha = 0.f;
    if (PRELU) alpha = __ldg(alpha_p);

    const int lane  = tid & 31;
    const int wid   = tid >> 5;
    const int half  = lane >> 4;
    const int lane16 = lane & 15;
    const int pbase = (wid << 3) + (half << 2);
    const int c4 = lane16 << 2;
    const int nchunks = (NND + 127) / 128;           // 782

    for (int chunk = blockIdx.x; chunk < nchunks; chunk += gridDim.x) {
        const int base = chunk * 128;
        __syncthreads();
        #pragma unroll
        for (int it = 0; it < 4; it++) {
            int idx = it * 256 + tid;
            int p  = idx >> 4;
            int kq = (idx & 15) << 2;
            int n0 = base + (p << 1), n1 = n0 + 1;
            float4 a0 = make_float4(0.f, 0.f, 0.f, 0.f);
            float4 a1 = make_float4(0.f, 0.f, 0.f, 0.f);
            if (n0 < NND) a0 = *(const float4*)&A[n0 * HID + kq];
            if (n1 < NND) a1 = *(const float4*)&A[n1 * HID + kq];
            ull* dst = &sAp[p * APSTRIDE1 + kq];
            dst[0] = packf2(a0.x, a1.x);
            dst[1] = packf2(a0.y, a1.y);
            dst[2] = packf2(a0.z, a1.z);
            dst[3] = packf2(a0.w, a1.w);
        }
        __syncthreads();

        ull acc[4][4];
        if (ACCUM) {
            #pragma unroll
            for (int i = 0; i < 4; i++) {
                int n0 = base + ((pbase + i) << 1), n1 = n0 + 1;
                float4 t0 = make_float4(0.f, 0.f, 0.f, 0.f);
                float4 t1 = make_float4(0.f, 0.f, 0.f, 0.f);
                if (n0 < NND) t0 = __ldg((const float4*)&acc_in[n0 * HID + c4]);
                if (n1 < NND) t1 = __ldg((const float4*)&acc_in[n1 * HID + c4]);
                acc[i][0] = packf2(t0.x, t1.x);
                acc[i][1] = packf2(t0.y, t1.y);
                acc[i][2] = packf2(t0.z, t1.z);
                acc[i][3] = packf2(t0.w, t1.w);
            }
        } else {
            float4 bv = __ldg((const float4*)&bb[c4]);
            #pragma unroll
            for (int i = 0; i < 4; i++) {
                acc[i][0] = pack2(bv.x); acc[i][1] = pack2(bv.y);
                acc[i][2] = pack2(bv.z); acc[i][3] = pack2(bv.w);
            }
        }

        #pragma unroll 4
        for (int kb = 0; kb < 64; kb += 2) {
            float4 w0 = *(const float4*)&sW[kb * 64 + c4];
            float4 w1 = *(const float4*)&sW[(kb + 1) * 64 + c4];
            ull wp0[4] = { pack2(w0.x), pack2(w0.y), pack2(w0.z), pack2(w0.w) };
            ull wp1[4] = { pack2(w1.x), pack2(w1.y), pack2(w1.z), pack2(w1.w) };
            ulonglong2 Ap[4];
            #pragma unroll
            for (int i = 0; i < 4; i++)
                Ap[i] = *(const ulonglong2*)&sAp[(pbase + i) * APSTRIDE1 + kb];
            #pragma unroll
            for (int i = 0; i < 4; i++) {
                fma2(acc[i][0], Ap[i].x, wp0[0]); fma2(acc[i][1], Ap[i].x, wp0[1]);
                fma2(acc[i][2], Ap[i].x, wp0[2]); fma2(acc[i][3], Ap[i].x, wp0[3]);
                fma2(acc[i][0], Ap[i].y, wp1[0]); fma2(acc[i][1], Ap[i].y, wp1[1]);
                fma2(acc[i][2], Ap[i].y, wp1[2]); fma2(acc[i][3], Ap[i].y, wp1[3]);
            }
        }

        #pragma unroll
        for (int i = 0; i < 4; i++) {
            int n0 = base + ((pbase + i) << 1), n1 = n0 + 1;
            float2 v0 = unpk(acc[i][0]), v1 = unpk(acc[i][1]);
            float2 v2 = unpk(acc[i][2]), v3 = unpk(acc[i][3]);
            if (PRELU) {
                v0.x = prelu(v0.x, alpha); v0.y = prelu(v0.y, alpha);
                v1.x = prelu(v1.x, alpha); v1.y = prelu(v1.y, alpha);
                v2.x = prelu(v2.x, alpha); v2.y = prelu(v2.y, alpha);
                v3.x = prelu(v3.x, alpha); v3.y = prelu(v3.y, alpha);
            }
            if (n0 < NND)
                *(float4*)&out[n0 * HID + c4] = make_float4(v0.x, v1.x, v2.x, v3.x);
            if (n1 < NND)
                *(float4*)&out[n1 * HID + c4] = make_float4(v0.y, v1.y, v2.y, v3.y);
        }
    }
}

// ---------------- launch: dual-stream fork/join schedule --------------------
extern "C" void kernel_launch(void* const* d_in, const int* in_sizes, int n_in,
                              void* d_out, int out_size) {
    const int*   x    = (const int*)d_in[0];
    const int*   ei   = (const int*)d_in[1];
    // d_in[2] = edge_weight : unused by the reference
    const float* emb  = (const float*)d_in[3];
    const float* Wl1  = (const float*)d_in[4];
    const float* bl1  = (const float*)d_in[5];
    const float* Wr1  = (const float*)d_in[6];
    const float* a1   = (const float*)d_in[7];
    const float* Wl2  = (const float*)d_in[8];
    const float* bl2  = (const float*)d_in[9];
    const float* Wr2  = (const float*)d_in[10];
    const float* a2   = (const float*)d_in[11];
    const float* Wout = (const float*)d_in[12];
    const float* bout = (const float*)d_in[13];
    float* out = (float*)d_out;

    float *h0, *h1, *agg, *tmp;
    cudaGetSymbolAddress((void**)&h0,  g_h0);
    cudaGetSymbolAddress((void**)&h1,  g_h1);
    cudaGetSymbolAddress((void**)&agg, g_agg);
    cudaGetSymbolAddress((void**)&tmp, g_tmp);

    // streams/events created once, on the uncaptured correctness call
    static cudaStream_t s2 = nullptr;
    static cudaEvent_t evF1 = nullptr, evJ1 = nullptr, evF2 = nullptr, evJ2 = nullptr;
    if (s2 == nullptr) {
        cudaStreamCreateWithFlags(&s2, cudaStreamNonBlocking);
        cudaEventCreateWithFlags(&evF1, cudaEventDisableTiming);
        cudaEventCreateWithFlags(&evJ1, cudaEventDisableTiming);
        cudaEventCreateWithFlags(&evF2, cudaEventDisableTiming);
        cudaEventCreateWithFlags(&evJ2, cudaEventDisableTiming);
    }

    const size_t smem_gemm = 64 * 64 * sizeof(float) + 64 * APSTRIDE1 * sizeof(ull); // ~50KB
    cudaFuncSetAttribute(gemm_pass_kernel<false, false>,
                         cudaFuncAttributeMaxDynamicSharedMemorySize, (int)smem_gemm);
    cudaFuncSetAttribute(gemm_pass_kernel<true, true>,
                         cudaFuncAttributeMaxDynamicSharedMemorySize, (int)smem_gemm);

    const int g_agg_grid = (NND * 16) / 256;   // 6250
    const int g_gemm = 782;

    // ---- fork 1: csr (s2)  ||  prep + h0@Wr1 (main) ----
    cudaEventRecord(evF1, 0);
    cudaStreamWaitEvent(s2, evF1, 0);
    csr_kernel<<<CSR_BLOCKS, CSR_THREADS, 0, s2>>>(ei);

    prep_kernel<<<g_agg_grid, 256>>>(x, emb, h0);
    gemm_pass_kernel<false, false><<<g_gemm, 256, smem_gemm>>>(
        h0, Wr1, bl1, nullptr, nullptr, tmp);

    cudaEventRecord(evJ1, s2);
    cudaStreamWaitEvent(0, evJ1, 0);

    // ---- layer 1 finish: agg(h0) -> h1 = prelu(agg@Wl1 + tmp) ----
    agg_kernel<<<g_agg_grid, 256>>>(h0, agg);
    gemm_pass_kernel<true, true><<<g_gemm, 256, smem_gemm>>>(
        agg, Wl1, nullptr, tmp, a1, h1);

    // ---- fork 2: h1@Wr2 (s2)  ||  agg(h1) (main) ----
    cudaEventRecord(evF2, 0);
    cudaStreamWaitEvent(s2, evF2, 0);
    gemm_pass_kernel<false, false><<<g_gemm, 256, smem_gemm, s2>>>(
        h1, Wr2, bl2, nullptr, nullptr, tmp);

    agg_kernel<<<g_agg_grid, 256>>>(h1, agg);

    cudaEventRecord(evJ2, s2);
    cudaStreamWaitEvent(0, evJ2, 0);

    // ---- layer 2 finish + output projection ----
    gemm_pass_kernel<true, true><<<g_gemm, 256, smem_gemm>>>(
        agg, Wl2, nullptr, tmp, a2, h0);
    gemm_pass_kernel<false, false><<<g_gemm, 256, smem_gemm>>>(
        h0, Wout, bout, nullptr, nullptr, out);
}